// round 16
// baseline (speedup 1.0000x reference)
#include <cuda_runtime.h>
#include <cuda_bf16.h>
#include <cstdint>
#include <cstddef>

// Problem constants
#define HDIM   512
#define BATCH  32
#define VOCAB  32000
#define MAXN   64
#define SOS_TOK 1

#define GRID   128
#define NTHR   512

// logits tiling
#define LROWS  256
#define NCAND  (VOCAB / LROWS)     // 125
#define MBLKS  (VOCAB / 16)        // 2000 16-row blocks
// gates tiling
#define GROWS  3072
#define KSPLIT 16
#define KSL    (HDIM / KSPLIT)     // 32
#define GATE_CTAS 96               // 6 rowblocks x 16 ksplits

// -------- persistent scratch --------
__device__ float g_h0[2][BATCH * HDIM];
__device__ float g_h1[2][BATCH * HDIM];
__device__ float g_part[KSPLIT * BATCH * GROWS];
__device__ float g_cval[NCAND * BATCH];
__device__ int   g_cidx[NCAND * BATCH];
__device__ volatile unsigned g_bar_count;

// W_out bf16x2 splits in MMA FRAGMENT ORDER (64MB total -> L2-resident)
#define WF_PER_SPLIT (MBLKS * 32 * 32)               // 2,048,000 uint4 (32MB)
__device__ __align__(16) uint4 g_Wf[2ull * WF_PER_SPLIT];

// -------- packed fp32x2 FMA --------
__device__ __forceinline__ float2 ffma2(float2 a, float2 b, float2 c) {
    unsigned long long ua = *reinterpret_cast<unsigned long long*>(&a);
    unsigned long long ub = *reinterpret_cast<unsigned long long*>(&b);
    unsigned long long uc = *reinterpret_cast<unsigned long long*>(&c);
    unsigned long long ud;
    asm("fma.rn.f32x2 %0, %1, %2, %3;" : "=l"(ud) : "l"(ua), "l"(ub), "l"(uc));
    return *reinterpret_cast<float2*>(&ud);
}

// -------- minimal-op fp64 transcendentals --------
__device__ __forceinline__ double exp_fast(double x) {
    double t = x * 1.4426950408889634;
    int    fn = __double2int_rn(t);
    double g  = (t - (double)fn) * 0.6931471805599453;
    double p  = 2.7557319223985893e-07;
    p = fma(p, g, 2.755731922398589e-06);
    p = fma(p, g, 2.4801587301587302e-05);
    p = fma(p, g, 1.9841269841269841e-04);
    p = fma(p, g, 1.3888888888888889e-03);
    p = fma(p, g, 8.3333333333333332e-03);
    p = fma(p, g, 4.1666666666666664e-02);
    p = fma(p, g, 1.6666666666666666e-01);
    p = fma(p, g, 0.5);
    p = fma(p, g, 1.0);
    p = fma(p, g, 1.0);
    return p * __longlong_as_double(((long long)(fn + 1023)) << 52);
}
__device__ __forceinline__ double rcp_fast(double u) {
    float rf;
    asm("rcp.approx.f32 %0, %1;" : "=f"(rf) : "f"((float)u));
    double r = (double)rf;
    r = fma(r, fma(-u, r, 1.0), r);
    r = fma(r, fma(-u, r, 1.0), r);
    return r;
}
__device__ __forceinline__ double sigmoid_fast(double x) { return rcp_fast(1.0 + exp_fast(-x)); }
__device__ __forceinline__ double tanh_fast(double y) {
    double a  = fabs(y);
    double e  = exp_fast(-2.0 * a);
    double th = (1.0 - e) * rcp_fast(1.0 + e);
    return (y < 0.0) ? -th : th;
}

#define MODE_INT_TOK   0
#define MODE_FLOAT_ALL 1
#define MODE_FLOAT_H   2

// -------- grid barrier --------
__device__ __forceinline__ void gbar(unsigned& epoch) {
    __threadfence();
    __syncthreads();
    if (threadIdx.x == 0) {
        epoch += 1;
        unsigned target = epoch * (unsigned)GRID;
        atomicAdd((unsigned*)&g_bar_count, 1u);
        while (g_bar_count < target) { }
        __threadfence();
    }
    __syncthreads();
}

// -------- warp-level bf16 MMA --------
__device__ __forceinline__ void mma_bf16(float* c, uint32_t a0, uint32_t a1,
                                         uint32_t a2, uint32_t a3,
                                         uint32_t b0, uint32_t b1) {
    asm volatile(
        "mma.sync.aligned.m16n8k16.row.col.f32.bf16.bf16.f32 "
        "{%0,%1,%2,%3}, {%4,%5,%6,%7}, {%8,%9}, {%0,%1,%2,%3};"
        : "+f"(c[0]), "+f"(c[1]), "+f"(c[2]), "+f"(c[3])
        : "r"(a0), "r"(a1), "r"(a2), "r"(a3), "r"(b0), "r"(b1));
}

// split a float pair into 3 packed bf16x2 levels
__device__ __forceinline__ void split2(float a, float b,
                                       uint32_t& o1, uint32_t& o2, uint32_t& o3) {
    __nv_bfloat16 a1 = __float2bfloat16(a), b1 = __float2bfloat16(b);
    float ar = a - __bfloat162float(a1), br = b - __bfloat162float(b1);
    __nv_bfloat16 a2 = __float2bfloat16(ar), b2 = __float2bfloat16(br);
    __nv_bfloat16 a3 = __float2bfloat16(ar - __bfloat162float(a2));
    __nv_bfloat16 b3 = __float2bfloat16(br - __bfloat162float(b2));
    __nv_bfloat162 t1 = __halves2bfloat162(a1, b1);
    __nv_bfloat162 t2 = __halves2bfloat162(a2, b2);
    __nv_bfloat162 t3 = __halves2bfloat162(a3, b3);
    o1 = *(unsigned*)&t1; o2 = *(unsigned*)&t2; o3 = *(unsigned*)&t3;
}

__device__ __forceinline__ void split8(const float* w, uint4& o1, uint4& o2, uint4& o3) {
    split2(w[0], w[1], o1.x, o2.x, o3.x);
    split2(w[2], w[3], o1.y, o2.y, o3.y);
    split2(w[4], w[5], o1.z, o2.z, o3.z);
    split2(w[6], w[7], o1.w, o2.w, o3.w);
}

// ---------------------------------------------------------------
__global__ void reset_kernel(const float* __restrict__ h0in) {
    int i = blockIdx.x * blockDim.x + threadIdx.x;
    if (i == 0) g_bar_count = 0;
    if (i < BATCH * HDIM) {
        g_h0[0][i] = h0in[i];
        g_h1[0][i] = h0in[BATCH * HDIM + i];
    }
}

// -------- smem layout (floats) --------
#define HS_STRIDE 260
#define HS_SPLIT  (BATCH * HS_STRIDE)        // 8320 b32 per split
#define HS_WORDS  (3 * HS_SPLIT)             // 24960
#define DS_OFF    HS_WORDS
#define SMEM_WORDS (HS_WORDS + LROWS * 33)   // 33408
#define SMEM_BYTES (SMEM_WORDS * 4)          // 133632

// ---------------------------------------------------------------
__global__ __launch_bounds__(NTHR, 1)
void decoder_kernel(const float* __restrict__ emb,
                    const float* __restrict__ Wih0, const float* __restrict__ Whh0,
                    const float* __restrict__ bih0, const float* __restrict__ bhh0,
                    const float* __restrict__ Wih1, const float* __restrict__ Whh1,
                    const float* __restrict__ bih1, const float* __restrict__ bhh1,
                    const float* __restrict__ Wout, const float* __restrict__ bout,
                    float* __restrict__ dout_f, int* __restrict__ dout_i, int mode)
{
    extern __shared__ float sm[];
    uint32_t* Hsm = (uint32_t*)sm;           // logits B splits (bf16x2 words)
    float*    Dsm = sm + DS_OFF;             // logits output tile
    float*    xs  = sm;                      // gates aliases
    float*    hs  = sm + BATCH * KSL;

    __shared__ float rv[NTHR];
    __shared__ int   ri[NTHR];
    __shared__ int   stok[BATCH];
    __shared__ float wval[8][BATCH];
    __shared__ int   widx[8][BATCH];

    const int cta = blockIdx.x;
    const int tid = threadIdx.x;
    const int wid = tid >> 5;
    const int lane = tid & 31;
    unsigned epoch = 0;

    // ======= prologue: W bf16x2 split into FRAGMENT order (once per launch) =======
    {
        const int NITEM = MBLKS * 32 * 32;            // 2,048,000
        for (int gi = cta * NTHR + tid; gi < NITEM; gi += GRID * NTHR) {
            int ln = gi & 31, ks = (gi >> 5) & 31, mb = gi >> 10;
            int gg = ln >> 2, tg2 = (ln & 3) * 2;
            const float* base = Wout + ((size_t)mb * 16 + gg) * HDIM + ks * 16;
            float2 f00 = *(const float2*)(base + tg2);
            float2 f10 = *(const float2*)(base + 8 * HDIM + tg2);
            float2 f01 = *(const float2*)(base + 8 + tg2);
            float2 f11 = *(const float2*)(base + 8 * HDIM + 8 + tg2);
            uint4 q1, q2, q3;
            split2(f00.x, f00.y, q1.x, q2.x, q3.x);
            split2(f10.x, f10.y, q1.y, q2.y, q3.y);
            split2(f01.x, f01.y, q1.z, q2.z, q3.z);
            split2(f11.x, f11.y, q1.w, q2.w, q3.w);
            size_t u = ((size_t)mb << 10) + ks * 32 + ln;
            g_Wf[0 * WF_PER_SPLIT + u] = q1;
            g_Wf[1 * WF_PER_SPLIT + u] = q2;
        }
    }
    gbar(epoch);

    for (int t = 0; t < MAXN; t++) {
        const int rp = t & 1, wp = 1 - rp;

        // ================= token resolve (16-way per batch) =================
        if (t == 0) {
            if (tid < BATCH) stok[tid] = SOS_TOK;
            __syncthreads();
        } else {
            const int b = tid >> 4, c16 = tid & 15;
            float best = -3.4e38f; int bi = 0x7fffffff;
            for (int cnd = c16; cnd < NCAND; cnd += 16) {
                float v  = __ldcg(&g_cval[cnd * BATCH + b]);
                int   ix = __ldcg(&g_cidx[cnd * BATCH + b]);
                if (v > best || (v == best && ix < bi)) { best = v; bi = ix; }
            }
            rv[tid] = best; ri[tid] = bi;
            __syncthreads();
            if (c16 == 0) {
                #pragma unroll
                for (int w = 1; w < 16; w++) {
                    float ov = rv[tid + w]; int oi = ri[tid + w];
                    if (ov > best || (ov == best && oi < bi)) { best = ov; bi = oi; }
                }
                stok[b] = bi;
                if (cta == 0) {
                    if (mode == MODE_INT_TOK)        dout_i[b * MAXN + (t - 1)] = bi;
                    else if (mode == MODE_FLOAT_ALL) dout_f[b * MAXN + (t - 1)] = (float)bi;
                }
            }
            __syncthreads();
        }

        // ================= two GRU layers (scalar, known-good) =================
        #pragma unroll 1
        for (int layer = 0; layer < 2; layer++) {
            const float* Wih = layer ? Wih1 : Wih0;
            const float* Whh = layer ? Whh1 : Whh0;

            if (cta < GATE_CTAS) {
                const int ks  = cta / 6;                 // 0..15
                const int row = (cta % 6) * NTHR + tid;  // 0..3071
                const bool xside = (row < 1536);
                const int wrow = xside ? row : (row - 1536);

                for (int i = tid; i < BATCH * (KSL / 4); i += NTHR) {   // 256 items
                    int b = i / (KSL / 4), f = i % (KSL / 4);
                    float4 xv;
                    if (layer == 0)
                        xv = *(const float4*)(emb + (size_t)stok[b] * HDIM + ks * KSL + f * 4);
                    else
                        xv = __ldcg((const float4*)(&g_h0[wp][0] + b * HDIM + ks * KSL + f * 4));
                    ((float4*)xs)[b * (KSL / 4) + f] = xv;
                    const float* hsrc = layer ? &g_h1[rp][0] : &g_h0[rp][0];
                    ((float4*)hs)[b * (KSL / 4) + f] =
                        __ldcg((const float4*)(hsrc + b * HDIM + ks * KSL + f * 4));
                }
                __syncthreads();

                const float4* W4   = (const float4*)((xside ? Wih : Whh) +
                                      (size_t)wrow * HDIM + ks * KSL);
                const float4* src4 = (const float4*)(xside ? xs : hs);

                float2 acc[BATCH];
                #pragma unroll
                for (int b = 0; b < BATCH; b++) acc[b] = make_float2(0.f, 0.f);

                #pragma unroll
                for (int c = 0; c < KSL / 16; c++) {     // 2 chunks of 16 k
                    float4 w0 = W4[c * 4 + 0], w1 = W4[c * 4 + 1];
                    float4 w2 = W4[c * 4 + 2], w3 = W4[c * 4 + 3];
                    float2 wl0 = make_float2(w0.x, w0.y), wh0 = make_float2(w0.z, w0.w);
                    float2 wl1 = make_float2(w1.x, w1.y), wh1 = make_float2(w1.z, w1.w);
                    float2 wl2 = make_float2(w2.x, w2.y), wh2 = make_float2(w2.z, w2.w);
                    float2 wl3 = make_float2(w3.x, w3.y), wh3 = make_float2(w3.z, w3.w);
                    #pragma unroll
                    for (int b = 0; b < BATCH; b++) {
                        const float4* hb = src4 + b * (KSL / 4) + c * 4;
                        float4 a0 = hb[0], a1 = hb[1], a2 = hb[2], a3 = hb[3];
                        float2 s = acc[b];
                        s = ffma2(wl0, make_float2(a0.x, a0.y), s);
                        s = ffma2(wh0, make_float2(a0.z, a0.w), s);
                        s = ffma2(wl1, make_float2(a1.x, a1.y), s);
                        s = ffma2(wh1, make_float2(a1.z, a1.w), s);
                        s = ffma2(wl2, make_float2(a2.x, a2.y), s);
                        s = ffma2(wh2, make_float2(a2.z, a2.w), s);
                        s = ffma2(wl3, make_float2(a3.x, a3.y), s);
                        s = ffma2(wh3, make_float2(a3.z, a3.w), s);
                        acc[b] = s;
                    }
                }

                #pragma unroll
                for (int b = 0; b < BATCH; b++)
                    __stcg(&g_part[(size_t)(ks * BATCH + b) * GROWS + row],
                           acc[b].x + acc[b].y);
            }
            gbar(epoch);

            // -------- activation: 512 elems per CTA, CTAs 0..31 --------
            if (cta < 32) {
                const int gt = cta * NTHR + tid;          // 0..16383
                const int b = gt >> 9, j = gt & 511;
                const float* bih = layer ? bih1 : bih0;
                const float* bhh = layer ? bhh1 : bhh0;

                float gir = 0.f, giz = 0.f, gin = 0.f, ghr = 0.f, ghz = 0.f, ghn = 0.f;
                #pragma unroll
                for (int kp = 0; kp < KSPLIT; kp++) {
                    const float* P = g_part + (size_t)(kp * BATCH + b) * GROWS;
                    gir += __ldcg(&P[j]);          giz += __ldcg(&P[j + 512]);
                    gin += __ldcg(&P[j + 1024]);   ghr += __ldcg(&P[1536 + j]);
                    ghz += __ldcg(&P[2048 + j]);   ghn += __ldcg(&P[2560 + j]);
                }
                gir += bih[j]; giz += bih[512 + j]; gin += bih[1024 + j];
                ghr += bhh[j]; ghz += bhh[512 + j]; ghn += bhh[1024 + j];

                float* hbuf = layer ? &g_h1[0][0] : &g_h0[0][0];
                float hprev = __ldcg(&hbuf[rp * BATCH * HDIM + b * HDIM + j]);

                double r = sigmoid_fast((double)(gir + ghr));
                double z = sigmoid_fast((double)(giz + ghz));
                double n = tanh_fast((double)gin + r * (double)ghn);
                __stcg(&hbuf[wp * BATCH * HDIM + b * HDIM + j],
                       (float)((1.0 - z) * n + z * (double)hprev));
            }
            gbar(epoch);
        }

        // ================= logits: bf16x2-stream + smem-h3 via mma.sync =================
        if (cta < NCAND) {
            const int v0 = cta * LROWS;
            const int g  = lane >> 2;
            const int tg = lane & 3;

            // ---- stage h splits into padded smem (B operand, 3 levels) ----
            {
                const float* hsrc = &g_h1[wp][0];
                for (int i = tid; i < 2048; i += NTHR) {
                    int b = i >> 6, kg = i & 63;
                    float4 f0 = __ldcg((const float4*)(hsrc + b * HDIM + kg * 8));
                    float4 f1 = __ldcg((const float4*)(hsrc + b * HDIM + kg * 8 + 4));
                    float w[8] = {f0.x, f0.y, f0.z, f0.w, f1.x, f1.y, f1.z, f1.w};
                    uint4 o1, o2, o3; split8(w, o1, o2, o3);
                    ((uint4*)Hsm)[(0 * HS_SPLIT + b * HS_STRIDE) / 4 + kg] = o1;
                    ((uint4*)Hsm)[(1 * HS_SPLIT + b * HS_STRIDE) / 4 + kg] = o2;
                    ((uint4*)Hsm)[(2 * HS_SPLIT + b * HS_STRIDE) / 4 + kg] = o3;
                }
            }
            __syncthreads();

            // ---- mma mainloop: warp = 1 mblock (16 rows), 16 warps, N=32, K=512 ----
            const int mb = cta * 16 + wid;
            const uint4* Af0 = g_Wf + ((size_t)mb << 10) + lane;
            const uint4* Af1 = g_Wf + WF_PER_SPLIT + ((size_t)mb << 10) + lane;

            uint32_t Bb[4][3];
            #pragma unroll
            for (int nt = 0; nt < 4; nt++)
                #pragma unroll
                for (int s = 0; s < 3; s++)
                    Bb[nt][s] = s * HS_SPLIT + (nt * 8 + g) * HS_STRIDE + tg;

            float acc[4][4];
            #pragma unroll
            for (int nt = 0; nt < 4; nt++)
                #pragma unroll
                for (int q = 0; q < 4; q++) acc[nt][q] = 0.f;

            uint4 Ac0 = Af0[0], Ac1 = Af1[0];
            uint4 An0, An1;

            #pragma unroll 1
            for (int ks = 0; ks < 32; ks++) {
                if (ks + 1 < 32) {
                    An0 = Af0[(ks + 1) * 32];
                    An1 = Af1[(ks + 1) * 32];
                }
                uint32_t Bf[4][3][2];
                #pragma unroll
                for (int nt = 0; nt < 4; nt++)
                    #pragma unroll
                    for (int s = 0; s < 3; s++) {
                        Bf[nt][s][0] = Hsm[Bb[nt][s] + ks * 8];
                        Bf[nt][s][1] = Hsm[Bb[nt][s] + ks * 8 + 4];
                    }
                #pragma unroll
                for (int nt = 0; nt < 4; nt++) {
                    float* c = acc[nt];
                    mma_bf16(c, Ac0.x, Ac0.y, Ac0.z, Ac0.w, Bf[nt][0][0], Bf[nt][0][1]); // 11
                    mma_bf16(c, Ac0.x, Ac0.y, Ac0.z, Ac0.w, Bf[nt][1][0], Bf[nt][1][1]); // 12
                    mma_bf16(c, Ac1.x, Ac1.y, Ac1.z, Ac1.w, Bf[nt][0][0], Bf[nt][0][1]); // 21
                    mma_bf16(c, Ac1.x, Ac1.y, Ac1.z, Ac1.w, Bf[nt][1][0], Bf[nt][1][1]); // 22
                    mma_bf16(c, Ac0.x, Ac0.y, Ac0.z, Ac0.w, Bf[nt][2][0], Bf[nt][2][1]); // 13
                }
                Ac0 = An0; Ac1 = An1;
            }

            // ---- dump D tile to smem ----
            #pragma unroll
            for (int nt = 0; nt < 4; nt++) {
                int row = wid * 16 + g;
                int col = nt * 8 + 2 * tg;
                Dsm[row * 33 + col]           = acc[nt][0];
                Dsm[row * 33 + col + 1]       = acc[nt][1];
                Dsm[(row + 8) * 33 + col]     = acc[nt][2];
                Dsm[(row + 8) * 33 + col + 1] = acc[nt][3];
            }
            __syncthreads();

            // ---- argmax: threads 0..255 = vocab rows ----
            if (tid < LROWS) {
                const float bv = bout[v0 + tid];
                #pragma unroll
                for (int b = 0; b < BATCH; b++) {
                    float val = Dsm[tid * 33 + b] + bv;
                    int   idx = v0 + tid;
                    #pragma unroll
                    for (int m = 16; m > 0; m >>= 1) {
                        float ov = __shfl_xor_sync(0xffffffffu, val, m);
                        int   oi = __shfl_xor_sync(0xffffffffu, idx, m);
                        if (ov > val || (ov == val && oi < idx)) { val = ov; idx = oi; }
                    }
                    if (lane == 0) { wval[wid][b] = val; widx[wid][b] = idx; }
                }
            }
            __syncthreads();

            if (tid < BATCH) {
                int b = tid;
                float best = wval[0][b]; int bi = widx[0][b];
                #pragma unroll
                for (int ww = 1; ww < 8; ww++) {
                    float ov = wval[ww][b]; int oi = widx[ww][b];
                    if (ov > best || (ov == best && oi < bi)) { best = ov; bi = oi; }
                }
                __stcg(&g_cval[cta * BATCH + b], best);
                __stcg(&g_cidx[cta * BATCH + b], bi);
            }
        }
        gbar(epoch);
    }

    // ================= epilogue: token 63 + h_t =================
    if (cta == 0) {
        const int b = tid >> 4, c16 = tid & 15;
        float best = -3.4e38f; int bi = 0x7fffffff;
        for (int cnd = c16; cnd < NCAND; cnd += 16) {
            float v  = __ldcg(&g_cval[cnd * BATCH + b]);
            int   ix = __ldcg(&g_cidx[cnd * BATCH + b]);
            if (v > best || (v == best && ix < bi)) { best = v; bi = ix; }
        }
        rv[tid] = best; ri[tid] = bi;
        __syncthreads();
        if (c16 == 0) {
            #pragma unroll
            for (int w = 1; w < 16; w++) {
                float ov = rv[tid + w]; int oi = ri[tid + w];
                if (ov > best || (ov == best && oi < bi)) { best = ov; bi = oi; }
            }
            if (mode == MODE_INT_TOK)        dout_i[b * MAXN + (MAXN - 1)] = bi;
            else if (mode == MODE_FLOAT_ALL) dout_f[b * MAXN + (MAXN - 1)] = (float)bi;
        }
    }
    if (mode != MODE_INT_TOK && cta >= 1 && cta <= BATCH) {
        const int b = cta - 1;
        const int off = (mode == MODE_FLOAT_ALL) ? (BATCH * MAXN) : 0;
        for (int k = tid; k < HDIM; k += NTHR) {
            dout_f[off + b * HDIM + k]                = __ldcg(&g_h0[0][b * HDIM + k]);
            dout_f[off + BATCH * HDIM + b * HDIM + k] = __ldcg(&g_h1[0][b * HDIM + k]);
        }
    }
}

// ---------------------------------------------------------------
extern "C" void kernel_launch(void* const* d_in, const int* in_sizes, int n_in,
                              void* d_out, int out_size)
{
    const float* h0   = (const float*)d_in[0];
    const float* emb  = (const float*)d_in[1];
    const float* Wih0 = (const float*)d_in[2];
    const float* Whh0 = (const float*)d_in[3];
    const float* bih0 = (const float*)d_in[4];
    const float* bhh0 = (const float*)d_in[5];
    const float* Wih1 = (const float*)d_in[6];
    const float* Whh1 = (const float*)d_in[7];
    const float* bih1 = (const float*)d_in[8];
    const float* bhh1 = (const float*)d_in[9];
    const float* Wout = (const float*)d_in[10];
    const float* bout = (const float*)d_in[11];

    int mode;
    if (out_size == BATCH * MAXN)          mode = MODE_INT_TOK;
    else if (out_size == 2 * BATCH * HDIM) mode = MODE_FLOAT_H;
    else                                   mode = MODE_FLOAT_ALL;

    float* dof = (float*)d_out;
    int*   doi = (int*)d_out;

    cudaFuncSetAttribute(decoder_kernel, cudaFuncAttributeMaxDynamicSharedMemorySize,
                         SMEM_BYTES);

    reset_kernel<<<(BATCH * HDIM + 511) / 512, 512>>>(h0);
    decoder_kernel<<<GRID, NTHR, SMEM_BYTES>>>(emb, Wih0, Whh0, bih0, bhh0,
                                               Wih1, Whh1, bih1, bhh1,
                                               Wout, bout, dof, doi, mode);
}

// round 17
// speedup vs baseline: 1.3739x; 1.3739x over previous
#include <cuda_runtime.h>
#include <cuda_bf16.h>
#include <cstdint>
#include <cstddef>

// Problem constants
#define HDIM   512
#define BATCH  32
#define VOCAB  32000
#define MAXN   64
#define SOS_TOK 1

#define GRID   128
#define NTHR   256

// logits tiling
#define LROWS  256
#define NCAND  (VOCAB / LROWS)     // 125
#define MBLKS  (VOCAB / 16)        // 2000 16-row blocks
// gates tiling
#define GROWS  3072
#define KSPLIT 8
#define KSL    (HDIM / KSPLIT)     // 64
#define GATE_CTAS (GROWS / NTHR * KSPLIT)   // 96

// -------- persistent scratch --------
__device__ float g_h0[2][BATCH * HDIM];
__device__ float g_h1[2][BATCH * HDIM];
__device__ float g_part[KSPLIT * BATCH * GROWS];
__device__ float g_cval[NCAND * BATCH];
__device__ int   g_cidx[NCAND * BATCH];
__device__ volatile unsigned g_bar_count;

// W_out bf16x2 splits in MMA FRAGMENT ORDER (64MB total -> L2-resident)
#define WF_PER_SPLIT (MBLKS * 32 * 32)               // 2,048,000 uint4 (32MB)
__device__ __align__(16) uint4 g_Wf[2ull * WF_PER_SPLIT];

// -------- packed fp32x2 FMA --------
__device__ __forceinline__ float2 ffma2(float2 a, float2 b, float2 c) {
    unsigned long long ua = *reinterpret_cast<unsigned long long*>(&a);
    unsigned long long ub = *reinterpret_cast<unsigned long long*>(&b);
    unsigned long long uc = *reinterpret_cast<unsigned long long*>(&c);
    unsigned long long ud;
    asm("fma.rn.f32x2 %0, %1, %2, %3;" : "=l"(ud) : "l"(ua), "l"(ub), "l"(uc));
    return *reinterpret_cast<float2*>(&ud);
}

// -------- minimal-op fp64 transcendentals --------
__device__ __forceinline__ double exp_fast(double x) {
    double t = x * 1.4426950408889634;
    int    fn = __double2int_rn(t);
    double g  = (t - (double)fn) * 0.6931471805599453;
    double p  = 2.7557319223985893e-07;
    p = fma(p, g, 2.755731922398589e-06);
    p = fma(p, g, 2.4801587301587302e-05);
    p = fma(p, g, 1.9841269841269841e-04);
    p = fma(p, g, 1.3888888888888889e-03);
    p = fma(p, g, 8.3333333333333332e-03);
    p = fma(p, g, 4.1666666666666664e-02);
    p = fma(p, g, 1.6666666666666666e-01);
    p = fma(p, g, 0.5);
    p = fma(p, g, 1.0);
    p = fma(p, g, 1.0);
    return p * __longlong_as_double(((long long)(fn + 1023)) << 52);
}
__device__ __forceinline__ double rcp_fast(double u) {
    float rf;
    asm("rcp.approx.f32 %0, %1;" : "=f"(rf) : "f"((float)u));
    double r = (double)rf;
    r = fma(r, fma(-u, r, 1.0), r);
    r = fma(r, fma(-u, r, 1.0), r);
    return r;
}
__device__ __forceinline__ double sigmoid_fast(double x) { return rcp_fast(1.0 + exp_fast(-x)); }
__device__ __forceinline__ double tanh_fast(double y) {
    double a  = fabs(y);
    double e  = exp_fast(-2.0 * a);
    double th = (1.0 - e) * rcp_fast(1.0 + e);
    return (y < 0.0) ? -th : th;
}

#define MODE_INT_TOK   0
#define MODE_FLOAT_ALL 1
#define MODE_FLOAT_H   2

// -------- grid barrier --------
__device__ __forceinline__ void gbar(unsigned& epoch) {
    __threadfence();
    __syncthreads();
    if (threadIdx.x == 0) {
        epoch += 1;
        unsigned target = epoch * (unsigned)GRID;
        atomicAdd((unsigned*)&g_bar_count, 1u);
        while (g_bar_count < target) { }
        __threadfence();
    }
    __syncthreads();
}

// -------- warp-level bf16 MMA --------
__device__ __forceinline__ void mma_bf16(float* c, uint32_t a0, uint32_t a1,
                                         uint32_t a2, uint32_t a3,
                                         uint32_t b0, uint32_t b1) {
    asm volatile(
        "mma.sync.aligned.m16n8k16.row.col.f32.bf16.bf16.f32 "
        "{%0,%1,%2,%3}, {%4,%5,%6,%7}, {%8,%9}, {%0,%1,%2,%3};"
        : "+f"(c[0]), "+f"(c[1]), "+f"(c[2]), "+f"(c[3])
        : "r"(a0), "r"(a1), "r"(a2), "r"(a3), "r"(b0), "r"(b1));
}

// split a float pair into 3 packed bf16x2 levels
__device__ __forceinline__ void split2(float a, float b,
                                       uint32_t& o1, uint32_t& o2, uint32_t& o3) {
    __nv_bfloat16 a1 = __float2bfloat16(a), b1 = __float2bfloat16(b);
    float ar = a - __bfloat162float(a1), br = b - __bfloat162float(b1);
    __nv_bfloat16 a2 = __float2bfloat16(ar), b2 = __float2bfloat16(br);
    __nv_bfloat16 a3 = __float2bfloat16(ar - __bfloat162float(a2));
    __nv_bfloat16 b3 = __float2bfloat16(br - __bfloat162float(b2));
    __nv_bfloat162 t1 = __halves2bfloat162(a1, b1);
    __nv_bfloat162 t2 = __halves2bfloat162(a2, b2);
    __nv_bfloat162 t3 = __halves2bfloat162(a3, b3);
    o1 = *(unsigned*)&t1; o2 = *(unsigned*)&t2; o3 = *(unsigned*)&t3;
}

__device__ __forceinline__ void split8(const float* w, uint4& o1, uint4& o2, uint4& o3) {
    split2(w[0], w[1], o1.x, o2.x, o3.x);
    split2(w[2], w[3], o1.y, o2.y, o3.y);
    split2(w[4], w[5], o1.z, o2.z, o3.z);
    split2(w[6], w[7], o1.w, o2.w, o3.w);
}

// ---------------------------------------------------------------
__global__ void reset_kernel(const float* __restrict__ h0in) {
    int i = blockIdx.x * blockDim.x + threadIdx.x;
    if (i == 0) g_bar_count = 0;
    if (i < BATCH * HDIM) {
        g_h0[0][i] = h0in[i];
        g_h1[0][i] = h0in[BATCH * HDIM + i];
    }
}

// -------- smem layout (floats) --------
#define HS_STRIDE 260
#define HS_SPLIT  (BATCH * HS_STRIDE)        // 8320 b32 per split
#define HS_WORDS  (3 * HS_SPLIT)             // 24960
#define DS_OFF    HS_WORDS
#define SMEM_WORDS (HS_WORDS + LROWS * 33)   // 33408
#define SMEM_BYTES (SMEM_WORDS * 4)          // 133632

// ---------------------------------------------------------------
__global__ __launch_bounds__(NTHR, 1)
void decoder_kernel(const float* __restrict__ emb,
                    const float* __restrict__ Wih0, const float* __restrict__ Whh0,
                    const float* __restrict__ bih0, const float* __restrict__ bhh0,
                    const float* __restrict__ Wih1, const float* __restrict__ Whh1,
                    const float* __restrict__ bih1, const float* __restrict__ bhh1,
                    const float* __restrict__ Wout, const float* __restrict__ bout,
                    float* __restrict__ dout_f, int* __restrict__ dout_i, int mode)
{
    extern __shared__ float sm[];
    uint32_t* Hsm = (uint32_t*)sm;           // logits B splits (bf16x2 words)
    float*    Dsm = sm + DS_OFF;             // logits output tile
    float*    xs  = sm;                      // gates aliases
    float*    hs  = sm + BATCH * KSL;

    __shared__ float rv[NTHR];
    __shared__ int   ri[NTHR];
    __shared__ int   stok[BATCH];

    const int cta = blockIdx.x;
    const int tid = threadIdx.x;
    const int wid = tid >> 5;
    const int lane = tid & 31;
    unsigned epoch = 0;

    // ======= prologue: W bf16x2 split into FRAGMENT order (once per launch) =======
    {
        const int NITEM = MBLKS * 32 * 32;            // 2,048,000
        for (int gi = cta * NTHR + tid; gi < NITEM; gi += GRID * NTHR) {
            int ln = gi & 31, ks = (gi >> 5) & 31, mb = gi >> 10;
            int gg = ln >> 2, tg2 = (ln & 3) * 2;
            const float* base = Wout + ((size_t)mb * 16 + gg) * HDIM + ks * 16;
            float2 f00 = *(const float2*)(base + tg2);
            float2 f10 = *(const float2*)(base + 8 * HDIM + tg2);
            float2 f01 = *(const float2*)(base + 8 + tg2);
            float2 f11 = *(const float2*)(base + 8 * HDIM + 8 + tg2);
            uint4 q1, q2, q3;
            split2(f00.x, f00.y, q1.x, q2.x, q3.x);
            split2(f10.x, f10.y, q1.y, q2.y, q3.y);
            split2(f01.x, f01.y, q1.z, q2.z, q3.z);
            split2(f11.x, f11.y, q1.w, q2.w, q3.w);
            size_t u = ((size_t)mb << 10) + ks * 32 + ln;
            g_Wf[0 * WF_PER_SPLIT + u] = q1;
            g_Wf[1 * WF_PER_SPLIT + u] = q2;
        }
    }
    gbar(epoch);

    for (int t = 0; t < MAXN; t++) {
        const int rp = t & 1, wp = 1 - rp;

        // ================= token resolve =================
        if (t == 0) {
            if (tid < BATCH) stok[tid] = SOS_TOK;
            __syncthreads();
        } else {
            const int b = tid >> 3, c8 = tid & 7;
            float best = -3.4e38f; int bi = 0x7fffffff;
            for (int cnd = c8; cnd < NCAND; cnd += 8) {
                float v  = __ldcg(&g_cval[cnd * BATCH + b]);
                int   ix = __ldcg(&g_cidx[cnd * BATCH + b]);
                if (v > best || (v == best && ix < bi)) { best = v; bi = ix; }
            }
            rv[tid] = best; ri[tid] = bi;
            __syncthreads();
            if (c8 == 0) {
                #pragma unroll
                for (int w = 1; w < 8; w++) {
                    float ov = rv[tid + w]; int oi = ri[tid + w];
                    if (ov > best || (ov == best && oi < bi)) { best = ov; bi = oi; }
                }
                stok[b] = bi;
                if (cta == 0) {
                    if (mode == MODE_INT_TOK)        dout_i[b * MAXN + (t - 1)] = bi;
                    else if (mode == MODE_FLOAT_ALL) dout_f[b * MAXN + (t - 1)] = (float)bi;
                }
            }
            __syncthreads();
        }

        // ================= two GRU layers (scalar, known-good) =================
        #pragma unroll 1
        for (int layer = 0; layer < 2; layer++) {
            const float* Wih = layer ? Wih1 : Wih0;
            const float* Whh = layer ? Whh1 : Whh0;

            if (cta < GATE_CTAS) {
                const int ks  = cta / 12;
                const int row = (cta % 12) * NTHR + tid;
                const bool xside = (row < 1536);
                const int wrow = xside ? row : (row - 1536);

                for (int i = tid; i < BATCH * (KSL / 4); i += NTHR) {
                    int b = i / (KSL / 4), f = i % (KSL / 4);
                    float4 xv;
                    if (layer == 0)
                        xv = *(const float4*)(emb + (size_t)stok[b] * HDIM + ks * KSL + f * 4);
                    else
                        xv = __ldcg((const float4*)(&g_h0[wp][0] + b * HDIM + ks * KSL + f * 4));
                    ((float4*)xs)[b * (KSL / 4) + f] = xv;
                    const float* hsrc = layer ? &g_h1[rp][0] : &g_h0[rp][0];
                    ((float4*)hs)[b * (KSL / 4) + f] =
                        __ldcg((const float4*)(hsrc + b * HDIM + ks * KSL + f * 4));
                }
                __syncthreads();

                const float4* W4   = (const float4*)((xside ? Wih : Whh) +
                                      (size_t)wrow * HDIM + ks * KSL);
                const float4* src4 = (const float4*)(xside ? xs : hs);

                float2 acc[BATCH];
                #pragma unroll
                for (int b = 0; b < BATCH; b++) acc[b] = make_float2(0.f, 0.f);

                #pragma unroll
                for (int c = 0; c < KSL / 16; c++) {
                    float4 w0 = W4[c * 4 + 0], w1 = W4[c * 4 + 1];
                    float4 w2 = W4[c * 4 + 2], w3 = W4[c * 4 + 3];
                    float2 wl0 = make_float2(w0.x, w0.y), wh0 = make_float2(w0.z, w0.w);
                    float2 wl1 = make_float2(w1.x, w1.y), wh1 = make_float2(w1.z, w1.w);
                    float2 wl2 = make_float2(w2.x, w2.y), wh2 = make_float2(w2.z, w2.w);
                    float2 wl3 = make_float2(w3.x, w3.y), wh3 = make_float2(w3.z, w3.w);
                    #pragma unroll
                    for (int b = 0; b < BATCH; b++) {
                        const float4* hb = src4 + b * (KSL / 4) + c * 4;
                        float4 a0 = hb[0], a1 = hb[1], a2 = hb[2], a3 = hb[3];
                        float2 s = acc[b];
                        s = ffma2(wl0, make_float2(a0.x, a0.y), s);
                        s = ffma2(wh0, make_float2(a0.z, a0.w), s);
                        s = ffma2(wl1, make_float2(a1.x, a1.y), s);
                        s = ffma2(wh1, make_float2(a1.z, a1.w), s);
                        s = ffma2(wl2, make_float2(a2.x, a2.y), s);
                        s = ffma2(wh2, make_float2(a2.z, a2.w), s);
                        s = ffma2(wl3, make_float2(a3.x, a3.y), s);
                        s = ffma2(wh3, make_float2(a3.z, a3.w), s);
                        acc[b] = s;
                    }
                }

                #pragma unroll
                for (int b = 0; b < BATCH; b++)
                    __stcg(&g_part[(size_t)(ks * BATCH + b) * GROWS + row],
                           acc[b].x + acc[b].y);
            }
            gbar(epoch);

            if (tid < 128) {
                const int gt = cta * 128 + tid;
                const int b = gt >> 9, j = gt & 511;
                const float* bih = layer ? bih1 : bih0;
                const float* bhh = layer ? bhh1 : bhh0;

                float gir = 0.f, giz = 0.f, gin = 0.f, ghr = 0.f, ghz = 0.f, ghn = 0.f;
                #pragma unroll
                for (int kp = 0; kp < KSPLIT; kp++) {
                    const float* P = g_part + (size_t)(kp * BATCH + b) * GROWS;
                    gir += __ldcg(&P[j]);          giz += __ldcg(&P[j + 512]);
                    gin += __ldcg(&P[j + 1024]);   ghr += __ldcg(&P[1536 + j]);
                    ghz += __ldcg(&P[2048 + j]);   ghn += __ldcg(&P[2560 + j]);
                }
                gir += bih[j]; giz += bih[512 + j]; gin += bih[1024 + j];
                ghr += bhh[j]; ghz += bhh[512 + j]; ghn += bhh[1024 + j];

                float* hbuf = layer ? &g_h1[0][0] : &g_h0[0][0];
                float hprev = __ldcg(&hbuf[rp * BATCH * HDIM + b * HDIM + j]);

                double r = sigmoid_fast((double)(gir + ghr));
                double z = sigmoid_fast((double)(giz + ghz));
                double n = tanh_fast((double)gin + r * (double)ghn);
                __stcg(&hbuf[wp * BATCH * HDIM + b * HDIM + j],
                       (float)((1.0 - z) * n + z * (double)hprev));
            }
            gbar(epoch);
        }

        // ================= logits: bf16x2-stream + smem-h3, distance-2 prefetch =================
        if (cta < NCAND) {
            const int v0 = cta * LROWS;
            const int g  = lane >> 2;
            const int tg = lane & 3;

            // ---- stage h splits into padded smem (B operand, 3 levels) ----
            {
                const float* hsrc = &g_h1[wp][0];
                for (int i = tid; i < 2048; i += NTHR) {
                    int b = i >> 6, kg = i & 63;
                    float4 f0 = __ldcg((const float4*)(hsrc + b * HDIM + kg * 8));
                    float4 f1 = __ldcg((const float4*)(hsrc + b * HDIM + kg * 8 + 4));
                    float w[8] = {f0.x, f0.y, f0.z, f0.w, f1.x, f1.y, f1.z, f1.w};
                    uint4 o1, o2, o3; split8(w, o1, o2, o3);
                    ((uint4*)Hsm)[(0 * HS_SPLIT + b * HS_STRIDE) / 4 + kg] = o1;
                    ((uint4*)Hsm)[(1 * HS_SPLIT + b * HS_STRIDE) / 4 + kg] = o2;
                    ((uint4*)Hsm)[(2 * HS_SPLIT + b * HS_STRIDE) / 4 + kg] = o3;
                }
            }
            __syncthreads();

            // ---- mma mainloop: warp = 32 vocab rows (2 M-tiles), N=32, K=512 ----
            const uint4* Af[2][2];
            #pragma unroll
            for (int mt = 0; mt < 2; mt++) {
                int mb = cta * 16 + wid * 2 + mt;
                #pragma unroll
                for (int s = 0; s < 2; s++)
                    Af[mt][s] = g_Wf + (size_t)s * WF_PER_SPLIT + ((size_t)mb << 10) + lane;
            }
            uint32_t Bb[4][3];
            #pragma unroll
            for (int nt = 0; nt < 4; nt++)
                #pragma unroll
                for (int s = 0; s < 3; s++)
                    Bb[nt][s] = s * HS_SPLIT + (nt * 8 + g) * HS_STRIDE + tg;

            float acc[2][4][4];
            #pragma unroll
            for (int mt = 0; mt < 2; mt++)
                #pragma unroll
                for (int nt = 0; nt < 4; nt++)
                    #pragma unroll
                    for (int q = 0; q < 4; q++) acc[mt][nt][q] = 0.f;

            // distance-2 software pipeline on A fragments
            uint4 Aa[2][2], Ab[2][2], Acp[2][2];
            #pragma unroll
            for (int mt = 0; mt < 2; mt++)
                #pragma unroll
                for (int s = 0; s < 2; s++) {
                    Aa[mt][s] = Af[mt][s][0];
                    Ab[mt][s] = Af[mt][s][32];
                }

            #pragma unroll 1
            for (int ks = 0; ks < 32; ks++) {
                if (ks + 2 < 32) {
                    #pragma unroll
                    for (int mt = 0; mt < 2; mt++)
                        #pragma unroll
                        for (int s = 0; s < 2; s++)
                            Acp[mt][s] = Af[mt][s][(ks + 2) * 32];
                }
                uint32_t Bf[4][3][2];
                #pragma unroll
                for (int nt = 0; nt < 4; nt++)
                    #pragma unroll
                    for (int s = 0; s < 3; s++) {
                        Bf[nt][s][0] = Hsm[Bb[nt][s] + ks * 8];
                        Bf[nt][s][1] = Hsm[Bb[nt][s] + ks * 8 + 4];
                    }
                #pragma unroll
                for (int mt = 0; mt < 2; mt++)
                    #pragma unroll
                    for (int nt = 0; nt < 4; nt++) {
                        float* c = acc[mt][nt];
                        uint4 A1 = Aa[mt][0], A2 = Aa[mt][1];
                        mma_bf16(c, A1.x, A1.y, A1.z, A1.w, Bf[nt][0][0], Bf[nt][0][1]); // 11
                        mma_bf16(c, A1.x, A1.y, A1.z, A1.w, Bf[nt][1][0], Bf[nt][1][1]); // 12
                        mma_bf16(c, A2.x, A2.y, A2.z, A2.w, Bf[nt][0][0], Bf[nt][0][1]); // 21
                        mma_bf16(c, A2.x, A2.y, A2.z, A2.w, Bf[nt][1][0], Bf[nt][1][1]); // 22
                        mma_bf16(c, A1.x, A1.y, A1.z, A1.w, Bf[nt][2][0], Bf[nt][2][1]); // 13
                    }
                #pragma unroll
                for (int mt = 0; mt < 2; mt++)
                    #pragma unroll
                    for (int s = 0; s < 2; s++) {
                        Aa[mt][s] = Ab[mt][s];
                        Ab[mt][s] = Acp[mt][s];
                    }
            }

            // ---- dump D tile to smem ----
            #pragma unroll
            for (int mt = 0; mt < 2; mt++)
                #pragma unroll
                for (int nt = 0; nt < 4; nt++) {
                    int row = wid * 32 + mt * 16 + g;
                    int col = nt * 8 + 2 * tg;
                    Dsm[row * 33 + col]           = acc[mt][nt][0];
                    Dsm[row * 33 + col + 1]       = acc[mt][nt][1];
                    Dsm[(row + 8) * 33 + col]     = acc[mt][nt][2];
                    Dsm[(row + 8) * 33 + col + 1] = acc[mt][nt][3];
                }
            __syncthreads();

            // ---- argmax: thread = vocab row ----
            __shared__ float wval[8][BATCH];
            __shared__ int   widx[8][BATCH];

            const float bv = bout[v0 + tid];
            #pragma unroll
            for (int b = 0; b < BATCH; b++) {
                float val = Dsm[tid * 33 + b] + bv;
                int   idx = v0 + tid;
                #pragma unroll
                for (int m = 16; m > 0; m >>= 1) {
                    float ov = __shfl_xor_sync(0xffffffffu, val, m);
                    int   oi = __shfl_xor_sync(0xffffffffu, idx, m);
                    if (ov > val || (ov == val && oi < idx)) { val = ov; idx = oi; }
                }
                if (lane == 0) { wval[wid][b] = val; widx[wid][b] = idx; }
            }
            __syncthreads();

            if (tid < BATCH) {
                int b = tid;
                float best = wval[0][b]; int bi = widx[0][b];
                #pragma unroll
                for (int ww = 1; ww < 8; ww++) {
                    float ov = wval[ww][b]; int oi = widx[ww][b];
                    if (ov > best || (ov == best && oi < bi)) { best = ov; bi = oi; }
                }
                __stcg(&g_cval[cta * BATCH + b], best);
                __stcg(&g_cidx[cta * BATCH + b], bi);
            }
        }
        gbar(epoch);
    }

    // ================= epilogue: token 63 + h_t =================
    if (cta == 0) {
        const int b = tid >> 3, c8 = tid & 7;
        float best = -3.4e38f; int bi = 0x7fffffff;
        for (int cnd = c8; cnd < NCAND; cnd += 8) {
            float v  = __ldcg(&g_cval[cnd * BATCH + b]);
            int   ix = __ldcg(&g_cidx[cnd * BATCH + b]);
            if (v > best || (v == best && ix < bi)) { best = v; bi = ix; }
        }
        rv[tid] = best; ri[tid] = bi;
        __syncthreads();
        if (c8 == 0) {
            #pragma unroll
            for (int w = 1; w < 8; w++) {
                float ov = rv[tid + w]; int oi = ri[tid + w];
                if (ov > best || (ov == best && oi < bi)) { best = ov; bi = oi; }
            }
            if (mode == MODE_INT_TOK)        dout_i[b * MAXN + (MAXN - 1)] = bi;
            else if (mode == MODE_FLOAT_ALL) dout_f[b * MAXN + (MAXN - 1)] = (float)bi;
        }
    }
    if (mode != MODE_INT_TOK && cta >= 1 && cta <= BATCH) {
        const int b = cta - 1;
        const int off = (mode == MODE_FLOAT_ALL) ? (BATCH * MAXN) : 0;
        for (int k = tid; k < HDIM; k += NTHR) {
            dout_f[off + b * HDIM + k]                = __ldcg(&g_h0[0][b * HDIM + k]);
            dout_f[off + BATCH * HDIM + b * HDIM + k] = __ldcg(&g_h1[0][b * HDIM + k]);
        }
    }
}

// ---------------------------------------------------------------
extern "C" void kernel_launch(void* const* d_in, const int* in_sizes, int n_in,
                              void* d_out, int out_size)
{
    const float* h0   = (const float*)d_in[0];
    const float* emb  = (const float*)d_in[1];
    const float* Wih0 = (const float*)d_in[2];
    const float* Whh0 = (const float*)d_in[3];
    const float* bih0 = (const float*)d_in[4];
    const float* bhh0 = (const float*)d_in[5];
    const float* Wih1 = (const float*)d_in[6];
    const float* Whh1 = (const float*)d_in[7];
    const float* bih1 = (const float*)d_in[8];
    const float* bhh1 = (const float*)d_in[9];
    const float* Wout = (const float*)d_in[10];
    const float* bout = (const float*)d_in[11];

    int mode;
    if (out_size == BATCH * MAXN)          mode = MODE_INT_TOK;
    else if (out_size == 2 * BATCH * HDIM) mode = MODE_FLOAT_H;
    else                                   mode = MODE_FLOAT_ALL;

    float* dof = (float*)d_out;
    int*   doi = (int*)d_out;

    cudaFuncSetAttribute(decoder_kernel, cudaFuncAttributeMaxDynamicSharedMemorySize,
                         SMEM_BYTES);

    reset_kernel<<<(BATCH * HDIM + 511) / 512, 512>>>(h0);
    decoder_kernel<<<GRID, NTHR, SMEM_BYTES>>>(emb, Wih0, Whh0, bih0, bhh0,
                                               Wih1, Whh1, bih1, bhh1,
                                               Wout, bout, dof, doi, mode);
}